// round 1
// baseline (speedup 1.0000x reference)
#include <cuda_runtime.h>
#include <cuda_bf16.h>

// Problem shape (fixed by the dataset's setup_inputs)
#define BB 4
#define LL 4096
#define MM 2048
#define DD 2048
#define CC 32          // number of chunks along M
#define TT 64          // chunk length = MM / CC
#define EPSF 1e-4f

// Scratch (device globals: no allocation allowed in kernel_launch)
__device__ float4 g_PADT[BB * MM];      // per (b,t): {p, a=1-p, dt, 1/dt}
__device__ int    g_POS [BB * MM];      // position l of the t-th boundary
__device__ int    g_count[BB];          // number of boundaries per batch
__device__ float  g_P  [BB * CC];       // per-chunk product of a
__device__ float  g_S  [BB * CC * DD];  // per-chunk partial (h with zero carry-in)
__device__ float  g_Hin[BB * CC * DD];  // per-chunk carry-in

// ---------------------------------------------------------------------------
// Setup: boundary scan, p gather (stable-sort semantics), per-chunk products.
// One block per batch, 512 threads, 8 tokens each.
// ---------------------------------------------------------------------------
__global__ void setup_kernel(const float* __restrict__ bp,
                             const void*  __restrict__ mask_raw)
{
    const int b   = blockIdx.x;
    const int tid = threadIdx.x;

    __shared__ int s_is32;
    __shared__ int s_cnt[512];

    // Probe mask dtype: int32 bools -> first 64 words all in {0,1};
    // packed uint8 bools (alternating / any mixed pattern) -> words > 1.
    if (tid == 0) {
        const int* w = (const int*)mask_raw;
        int ok = 1;
        for (int i = 0; i < 64; i++) {
            unsigned v = (unsigned)w[i];
            if (v > 1u) { ok = 0; break; }
        }
        s_is32 = ok;
    }
    __syncthreads();
    const bool is32 = (s_is32 != 0);

    // Load my 8 mask flags, local count
    int flags[8];
    const int base_l = tid * 8;
    int cnt = 0;
#pragma unroll
    for (int i = 0; i < 8; i++) {
        const int l = base_l + i;
        int f;
        if (is32) f = (((const int*)mask_raw)[b * LL + l] != 0);
        else      f = (((const unsigned char*)mask_raw)[b * LL + l] != 0);
        flags[i] = f;
        cnt += f;
    }
    s_cnt[tid] = cnt;
    __syncthreads();

    // Hillis-Steele inclusive scan over 512 per-thread counts
    for (int off = 1; off < 512; off <<= 1) {
        int v   = s_cnt[tid];
        int add = (tid >= off) ? s_cnt[tid - off] : 0;
        __syncthreads();
        s_cnt[tid] = v + add;
        __syncthreads();
    }
    const int total = s_cnt[511];
    int run = s_cnt[tid] - cnt;   // boundaries strictly before my first token
    if (tid == 0) g_count[b] = total;

    // Stable-sort position: boundaries first (in order), then non-boundaries.
#pragma unroll
    for (int i = 0; i < 8; i++) {
        const int l = base_l + i;
        int s;
        if (flags[i]) { s = run; run++; }
        else          { s = total + (l - run); }
        if (s < MM) {
            float p = bp[b * LL + l];
            p = fminf(fmaxf(p, EPSF), 1.0f - EPSF);
            const float a     = 1.0f - p;
            const float dt    = logf(1.0f / a);
            const float invdt = 1.0f / dt;
            g_PADT[b * MM + s] = make_float4(p, a, dt, invdt);
            if (flags[i]) g_POS[b * MM + s] = l;
        }
    }
    __syncthreads();   // make g_PADT writes visible block-wide

    // Per-chunk products of a (a <= 1-eps, underflow to 0 is benign/correct)
    if (tid < CC) {
        float prod = 1.0f;
        for (int i = 0; i < TT; i++)
            prod *= g_PADT[b * MM + tid * TT + i].y;
        g_P[b * CC + tid] = prod;
    }
}

// ---------------------------------------------------------------------------
// Pass 1: per-chunk partial EMA with zero carry-in -> g_S.
// Grid (DD/256, CC, BB), 256 threads, one d-channel per thread.
// ---------------------------------------------------------------------------
__global__ void pass1_kernel(const float* __restrict__ hid)
{
    const int d = blockIdx.x * 256 + threadIdx.x;
    const int c = blockIdx.y;
    const int b = blockIdx.z;

    __shared__ float4 sp[TT];
    if (threadIdx.x < TT)
        sp[threadIdx.x] = g_PADT[b * MM + c * TT + threadIdx.x];
    __syncthreads();

    const float* hptr = hid + ((size_t)(b * MM + c * TT)) * DD + d;
    float S = 0.0f;
#pragma unroll 8
    for (int t = 0; t < TT; t++) {
        const float4 q = sp[t];
        const float hval = hptr[(size_t)t * DD];
        const float hs   = (hval * q.w) * q.z;   // (h/dt)*dt fp roundtrip
        S = fmaf(q.y, S, q.x * hs);              // S = a*S + p*hs
    }
    g_S[(b * CC + c) * DD + d] = S;
}

// ---------------------------------------------------------------------------
// Pass 2: serial combine across chunks -> per-chunk carry-in g_Hin.
// Grid (DD/256, BB). Small (2 MB, L2-resident).
// ---------------------------------------------------------------------------
__global__ void pass2_kernel()
{
    const int d = blockIdx.x * 256 + threadIdx.x;
    const int b = blockIdx.y;
    float h = 0.0f;
#pragma unroll 1
    for (int c = 0; c < CC; c++) {
        const int idx = (b * CC + c) * DD + d;
        g_Hin[idx] = h;
        h = fmaf(g_P[b * CC + c], h, g_S[idx]);
    }
}

// ---------------------------------------------------------------------------
// Pass 3: recompute in-chunk states with correct carry-in, expand to out.
// hidden re-read should hit L2; out written with streaming stores.
// ---------------------------------------------------------------------------
__global__ void pass3_kernel(const float* __restrict__ hid,
                             float* __restrict__ out)
{
    const int d   = blockIdx.x * 256 + threadIdx.x;
    const int c   = blockIdx.y;
    const int b   = blockIdx.z;
    const int tid = threadIdx.x;

    __shared__ float4 sp[TT];
    __shared__ int    spos[TT + 1];
    __shared__ int    s_cnt_sh;

    if (tid < TT) sp[tid] = g_PADT[b * MM + c * TT + tid];
    if (tid <= TT) {
        const int idx = c * TT + tid;
        spos[tid] = (idx < MM) ? g_POS[b * MM + idx] : LL;
    }
    if (tid == 255) s_cnt_sh = min(g_count[b], MM);
    __syncthreads();
    const int cnt = s_cnt_sh;

    const float* hptr = hid + ((size_t)(b * MM + c * TT)) * DD + d;
    float h = g_Hin[(b * CC + c) * DD + d];
    float* outb = out + (size_t)b * LL * DD + d;

#pragma unroll 2
    for (int t = 0; t < TT; t++) {
        const float4 q = sp[t];
        const float hval = hptr[(size_t)t * DD];
        const float hs   = (hval * q.w) * q.z;
        h = fmaf(q.y, h, q.x * hs);

        const int tg = c * TT + t;
        if (tg < cnt) {
            const int start = spos[t];
            const int end   = (tg + 1 < cnt) ? spos[t + 1] : LL;
            for (int l = start; l < end; l++) {
                __stcs(outb + (size_t)l * DD, h);   // streaming: don't pollute L2
            }
        }
    }
}

// ---------------------------------------------------------------------------
// Inputs (metadata order = setup_inputs dict order):
//   d_in[0] hidden_states  float32 (B,M,D)
//   d_in[1] boundary_prob  float32 (B,L)
//   d_in[2] boundary_mask  bool    (B,L)  (dtype probed device-side)
//   d_in[3] mask                    -- unused by the reference
// Output: float32 (B,L,D)
// ---------------------------------------------------------------------------
extern "C" void kernel_launch(void* const* d_in, const int* in_sizes, int n_in,
                              void* d_out, int out_size)
{
    const float* hid = (const float*)d_in[0];
    const float* bp  = (const float*)d_in[1];
    const void*  bm  = d_in[2];
    float* out = (float*)d_out;

    setup_kernel<<<BB, 512>>>(bp, bm);
    pass1_kernel<<<dim3(DD / 256, CC, BB), 256>>>(hid);
    pass2_kernel<<<dim3(DD / 256, BB), 256>>>();
    pass3_kernel<<<dim3(DD / 256, CC, BB), 256>>>(hid, out);
}

// round 2
// speedup vs baseline: 1.0766x; 1.0766x over previous
#include <cuda_runtime.h>
#include <cuda_bf16.h>

// Problem shape (fixed by the dataset's setup_inputs)
#define BB 4
#define LL 4096
#define MM 2048
#define DD 2048
#define D4 (DD / 4)    // 512 float4 lanes
#define CC 64          // number of chunks along M
#define TT 32          // chunk length = MM / CC
#define EPSF 1e-4f

// Scratch (device globals: no allocation allowed in kernel_launch)
__device__ float4 g_PADT[BB * MM];        // per (b,t): {p, a=1-p, dt, 1/dt}
__device__ int    g_POS [BB * MM];        // position l of the t-th boundary
__device__ int    g_count[BB];            // number of boundaries per batch
__device__ float  g_P  [BB * CC];         // per-chunk product of a
__device__ float4 g_S4 [BB * CC * D4];    // per-chunk partial (zero carry-in)
__device__ float4 g_Hin4[BB * CC * D4];   // per-chunk carry-in

// ---------------------------------------------------------------------------
// Setup: boundary scan, p gather (stable-sort semantics), per-chunk products.
// One block per batch, 512 threads, 8 tokens each.
// ---------------------------------------------------------------------------
__global__ void setup_kernel(const float* __restrict__ bp,
                             const void*  __restrict__ mask_raw)
{
    const int b   = blockIdx.x;
    const int tid = threadIdx.x;

    __shared__ int s_is32;
    __shared__ int s_cnt[512];

    // Probe mask dtype: int32 bools -> first 64 words all in {0,1};
    // packed uint8 bools (mixed pattern) -> some word > 1.
    if (tid == 0) {
        const int* w = (const int*)mask_raw;
        int ok = 1;
        for (int i = 0; i < 64; i++) {
            unsigned v = (unsigned)w[i];
            if (v > 1u) { ok = 0; break; }
        }
        s_is32 = ok;
    }
    __syncthreads();
    const bool is32 = (s_is32 != 0);

    int flags[8];
    const int base_l = tid * 8;
    int cnt = 0;
#pragma unroll
    for (int i = 0; i < 8; i++) {
        const int l = base_l + i;
        int f;
        if (is32) f = (((const int*)mask_raw)[b * LL + l] != 0);
        else      f = (((const unsigned char*)mask_raw)[b * LL + l] != 0);
        flags[i] = f;
        cnt += f;
    }
    s_cnt[tid] = cnt;
    __syncthreads();

    // Hillis-Steele inclusive scan over 512 per-thread counts
    for (int off = 1; off < 512; off <<= 1) {
        int v   = s_cnt[tid];
        int add = (tid >= off) ? s_cnt[tid - off] : 0;
        __syncthreads();
        s_cnt[tid] = v + add;
        __syncthreads();
    }
    const int total = s_cnt[511];
    int run = s_cnt[tid] - cnt;   // boundaries strictly before my first token
    if (tid == 0) g_count[b] = total;

    // Stable-sort position: boundaries first (in order), then non-boundaries.
#pragma unroll
    for (int i = 0; i < 8; i++) {
        const int l = base_l + i;
        int s;
        if (flags[i]) { s = run; run++; }
        else          { s = total + (l - run); }
        if (s < MM) {
            float p = bp[b * LL + l];
            p = fminf(fmaxf(p, EPSF), 1.0f - EPSF);
            const float a     = 1.0f - p;
            const float dt    = logf(1.0f / a);
            const float invdt = 1.0f / dt;
            g_PADT[b * MM + s] = make_float4(p, a, dt, invdt);
            if (flags[i]) g_POS[b * MM + s] = l;
        }
    }
    __syncthreads();

    // Per-chunk products of a (a <= 1-eps, underflow to 0 is benign/correct)
    if (tid < CC) {
        float prod = 1.0f;
        for (int i = 0; i < TT; i++)
            prod *= g_PADT[b * MM + tid * TT + i].y;
        g_P[b * CC + tid] = prod;
    }
}

// ---------------------------------------------------------------------------
// Pass 1: per-chunk partial EMA with zero carry-in -> g_S4.
// Grid (D4/256, CC, BB), 256 threads, one float4 d-lane per thread.
// ---------------------------------------------------------------------------
__global__ void pass1_kernel(const float4* __restrict__ hid4)
{
    const int d4 = blockIdx.x * 256 + threadIdx.x;
    const int c  = blockIdx.y;
    const int b  = blockIdx.z;

    __shared__ float4 sp[TT];
    if (threadIdx.x < TT)
        sp[threadIdx.x] = g_PADT[b * MM + c * TT + threadIdx.x];
    __syncthreads();

    const float4* hptr = hid4 + (size_t)(b * MM + c * TT) * D4 + d4;
    float4 S = make_float4(0.f, 0.f, 0.f, 0.f);
#pragma unroll 8
    for (int t = 0; t < TT; t++) {
        const float4 q  = sp[t];
        const float4 hv = __ldcg(hptr + (size_t)t * D4);   // L2-resident for pass3
        S.x = fmaf(q.y, S.x, q.x * ((hv.x * q.w) * q.z));
        S.y = fmaf(q.y, S.y, q.x * ((hv.y * q.w) * q.z));
        S.z = fmaf(q.y, S.z, q.x * ((hv.z * q.w) * q.z));
        S.w = fmaf(q.y, S.w, q.x * ((hv.w * q.w) * q.z));
    }
    g_S4[(b * CC + c) * D4 + d4] = S;
}

// ---------------------------------------------------------------------------
// Pass 2: serial combine across chunks -> per-chunk carry-in g_Hin4.
// Grid (D4/256, BB). Small (8 MB total, L2-resident).
// ---------------------------------------------------------------------------
__global__ void pass2_kernel()
{
    const int d4 = blockIdx.x * 256 + threadIdx.x;
    const int b  = blockIdx.y;

    __shared__ float sP[CC];
    if (threadIdx.x < CC) sP[threadIdx.x] = g_P[b * CC + threadIdx.x];
    __syncthreads();

    float4 h = make_float4(0.f, 0.f, 0.f, 0.f);
#pragma unroll 1
    for (int c = 0; c < CC; c++) {
        const int idx = (b * CC + c) * D4 + d4;
        g_Hin4[idx] = h;
        const float4 S = g_S4[idx];
        const float  P = sP[c];
        h.x = fmaf(P, h.x, S.x);
        h.y = fmaf(P, h.y, S.y);
        h.z = fmaf(P, h.z, S.z);
        h.w = fmaf(P, h.w, S.w);
    }
}

// ---------------------------------------------------------------------------
// Pass 3: recompute in-chunk states with correct carry-in, expand to out.
// Hidden re-read hits L2 (left there by pass1); output via float4 streaming.
// ---------------------------------------------------------------------------
__global__ void pass3_kernel(const float4* __restrict__ hid4,
                             float4* __restrict__ out4)
{
    const int d4  = blockIdx.x * 256 + threadIdx.x;
    const int c   = blockIdx.y;
    const int b   = blockIdx.z;
    const int tid = threadIdx.x;

    __shared__ float4 sp[TT];
    __shared__ int    spos[TT + 1];
    __shared__ int    s_cnt_sh;

    if (tid < TT) sp[tid] = g_PADT[b * MM + c * TT + tid];
    if (tid <= TT) {
        const int idx = c * TT + tid;
        spos[tid] = (idx < MM) ? g_POS[b * MM + idx] : LL;
    }
    if (tid == 255) s_cnt_sh = min(g_count[b], MM);
    __syncthreads();
    const int cnt = s_cnt_sh;

    const float4* hptr = hid4 + (size_t)(b * MM + c * TT) * D4 + d4;
    float4 h = g_Hin4[(b * CC + c) * D4 + d4];
    float4* outb = out4 + (size_t)b * LL * D4 + d4;

#pragma unroll 4
    for (int t = 0; t < TT; t++) {
        const float4 q  = sp[t];
        const float4 hv = __ldcg(hptr + (size_t)t * D4);
        h.x = fmaf(q.y, h.x, q.x * ((hv.x * q.w) * q.z));
        h.y = fmaf(q.y, h.y, q.x * ((hv.y * q.w) * q.z));
        h.z = fmaf(q.y, h.z, q.x * ((hv.z * q.w) * q.z));
        h.w = fmaf(q.y, h.w, q.x * ((hv.w * q.w) * q.z));

        const int tg = c * TT + t;
        if (tg < cnt) {
            const int start = spos[t];
            const int end   = (tg + 1 < cnt) ? spos[t + 1] : LL;
            for (int l = start; l < end; l++) {
                __stcs(outb + (size_t)l * D4, h);   // streaming 16B store
            }
        }
    }
}

// ---------------------------------------------------------------------------
// Inputs (metadata order = setup_inputs dict order):
//   d_in[0] hidden_states  float32 (B,M,D)
//   d_in[1] boundary_prob  float32 (B,L)
//   d_in[2] boundary_mask  bool    (B,L)  (dtype probed device-side)
//   d_in[3] mask                    -- unused by the reference
// Output: float32 (B,L,D)
// ---------------------------------------------------------------------------
extern "C" void kernel_launch(void* const* d_in, const int* in_sizes, int n_in,
                              void* d_out, int out_size)
{
    const float4* hid4 = (const float4*)d_in[0];
    const float*  bp   = (const float*)d_in[1];
    const void*   bm   = d_in[2];
    float4* out4 = (float4*)d_out;

    setup_kernel<<<BB, 512>>>(bp, bm);
    pass1_kernel<<<dim3(D4 / 256, CC, BB), 256>>>(hid4);
    pass2_kernel<<<dim3(D4 / 256, BB), 256>>>();
    pass3_kernel<<<dim3(D4 / 256, CC, BB), 256>>>(hid4, out4);
}

// round 5
// speedup vs baseline: 1.3792x; 1.2811x over previous
#include <cuda_runtime.h>
#include <cuda_bf16.h>

// Problem shape (fixed by the dataset's setup_inputs)
#define BB 4
#define LL 4096
#define MM 2048
#define DD 2048
#define D4 (DD / 4)        // 512 float4 lanes
#define CC 128             // chunks along M
#define TT 16              // chunk length = MM / CC
#define NSUP 8             // superchunks
#define SUPLEN 16          // chunks per superchunk
#define EPSF 1e-4f

// Scratch (device globals: no allocation allowed in kernel_launch)
__device__ float4 g_PADT[BB * MM];          // per (b,t): {p, a=1-p, dt, 1/dt}
__device__ int    g_POS [BB * MM];          // position l of the t-th boundary
__device__ int    g_count[BB];              // boundaries per batch
__device__ float  g_P   [BB * CC];          // per-chunk product of a
__device__ float  g_W   [BB * CC];          // prefix product within superchunk
__device__ float  g_Psup[BB * NSUP];        // per-superchunk product of a
__device__ float4 g_S4  [BB * CC * D4];     // per-chunk partial (zero carry-in)
__device__ float4 g_Hin4[BB * CC * D4];     // carry-in LOCAL to superchunk
__device__ float4 g_Ssup[BB * NSUP * D4];   // superchunk partial (zero carry-in)
__device__ float4 g_Hsup[BB * NSUP * D4];   // superchunk carry-in

// ---------------------------------------------------------------------------
// Setup: boundary scan, p gather (stable-sort semantics), scalar products.
// One block per batch, 512 threads, 8 tokens each.
// ---------------------------------------------------------------------------
__global__ void setup_kernel(const float* __restrict__ bp,
                             const void*  __restrict__ mask_raw)
{
    const int b   = blockIdx.x;
    const int tid = threadIdx.x;

    __shared__ int   s_is32;
    __shared__ int   s_cnt[512];
    __shared__ float s_a[MM];       // a = 1-p by sorted slot
    __shared__ float s_prod[CC];    // per-chunk products

    // Probe mask dtype: int32 bools -> first 64 words all in {0,1};
    // packed uint8 bools (mixed pattern) -> some word > 1.
    if (tid == 0) {
        const int* w = (const int*)mask_raw;
        int ok = 1;
        for (int i = 0; i < 64; i++) {
            unsigned v = (unsigned)w[i];
            if (v > 1u) { ok = 0; break; }
        }
        s_is32 = ok;
    }
    __syncthreads();
    const bool is32 = (s_is32 != 0);

    int flags[8];
    const int base_l = tid * 8;
    int cnt = 0;
#pragma unroll
    for (int i = 0; i < 8; i++) {
        const int l = base_l + i;
        int f;
        if (is32) f = (((const int*)mask_raw)[b * LL + l] != 0);
        else      f = (((const unsigned char*)mask_raw)[b * LL + l] != 0);
        flags[i] = f;
        cnt += f;
    }
    s_cnt[tid] = cnt;
    __syncthreads();

    // Hillis-Steele inclusive scan over 512 per-thread counts
    for (int off = 1; off < 512; off <<= 1) {
        int v   = s_cnt[tid];
        int add = (tid >= off) ? s_cnt[tid - off] : 0;
        __syncthreads();
        s_cnt[tid] = v + add;
        __syncthreads();
    }
    const int total = s_cnt[511];
    int run = s_cnt[tid] - cnt;    // boundaries strictly before my first token
    if (tid == 0) g_count[b] = total;

    // Stable-sort position: boundaries first (in order), then non-boundaries.
#pragma unroll
    for (int i = 0; i < 8; i++) {
        const int l = base_l + i;
        int s;
        if (flags[i]) { s = run; run++; }
        else          { s = total + (l - run); }
        if (s < MM) {
            float p = bp[b * LL + l];
            p = fminf(fmaxf(p, EPSF), 1.0f - EPSF);
            const float a     = 1.0f - p;
            const float dt    = logf(1.0f / a);
            const float invdt = 1.0f / dt;
            g_PADT[b * MM + s] = make_float4(p, a, dt, invdt);
            s_a[s] = a;
            if (flags[i]) g_POS[b * MM + s] = l;
        }
    }
    __syncthreads();

    // Per-chunk products of a from smem (a <= 1-eps; underflow benign)
    if (tid < CC) {
        float prod = 1.0f;
#pragma unroll
        for (int i = 0; i < TT; i++) prod *= s_a[tid * TT + i];
        s_prod[tid] = prod;
        g_P[b * CC + tid] = prod;
    }
    __syncthreads();

    // Prefix product within superchunk: W_c = prod over chunks [sup_start, c)
    if (tid < CC) {
        const int s0 = (tid / SUPLEN) * SUPLEN;
        float w = 1.0f;
        for (int k = s0; k < tid; k++) w *= s_prod[k];
        g_W[b * CC + tid] = w;
    }
    // Superchunk product
    if (tid < NSUP) {
        float ps = 1.0f;
#pragma unroll
        for (int k = 0; k < SUPLEN; k++) ps *= s_prod[tid * SUPLEN + k];
        g_Psup[b * NSUP + tid] = ps;
    }
}

// ---------------------------------------------------------------------------
// Pass 1: per-chunk partial EMA with zero carry-in -> g_S4.
// Grid (D4/256, CC, BB). Tile loads front-batched for MLP.
// ---------------------------------------------------------------------------
__global__ void pass1_kernel(const float4* __restrict__ hid4)
{
    const int d4 = blockIdx.x * 256 + threadIdx.x;
    const int c  = blockIdx.y;
    const int b  = blockIdx.z;

    __shared__ float4 sp[TT];
    if (threadIdx.x < TT)
        sp[threadIdx.x] = g_PADT[b * MM + c * TT + threadIdx.x];
    __syncthreads();

    const float4* hptr = hid4 + (size_t)(b * MM + c * TT) * D4 + d4;
    float4 hv[TT];
#pragma unroll
    for (int t = 0; t < TT; t++)
        hv[t] = __ldcg(hptr + (size_t)t * D4);   // L2-resident for pass3

    float4 S = make_float4(0.f, 0.f, 0.f, 0.f);
#pragma unroll
    for (int t = 0; t < TT; t++) {
        const float4 q = sp[t];
        S.x = fmaf(q.y, S.x, q.x * ((hv[t].x * q.w) * q.z));
        S.y = fmaf(q.y, S.y, q.x * ((hv[t].y * q.w) * q.z));
        S.z = fmaf(q.y, S.z, q.x * ((hv[t].z * q.w) * q.z));
        S.w = fmaf(q.y, S.w, q.x * ((hv[t].w * q.w) * q.z));
    }
    g_S4[(b * CC + c) * D4 + d4] = S;
}

// ---------------------------------------------------------------------------
// Pass 2a: within-superchunk scan. Grid (D4/256, NSUP, BB) = 256 blocks.
// Produces carry-in LOCAL to the superchunk + superchunk aggregate.
// ---------------------------------------------------------------------------
__global__ void pass2a_kernel()
{
    const int d4 = blockIdx.x * 256 + threadIdx.x;
    const int s  = blockIdx.y;
    const int b  = blockIdx.z;

    __shared__ float sP[SUPLEN];
    if (threadIdx.x < SUPLEN)
        sP[threadIdx.x] = g_P[b * CC + s * SUPLEN + threadIdx.x];
    __syncthreads();

    const int base = (b * CC + s * SUPLEN) * D4 + d4;
    float4 Sv[SUPLEN];
#pragma unroll
    for (int j = 0; j < SUPLEN; j++)
        Sv[j] = g_S4[base + j * D4];

    float4 h = make_float4(0.f, 0.f, 0.f, 0.f);
#pragma unroll
    for (int j = 0; j < SUPLEN; j++) {
        g_Hin4[base + j * D4] = h;
        const float P = sP[j];
        h.x = fmaf(P, h.x, Sv[j].x);
        h.y = fmaf(P, h.y, Sv[j].y);
        h.z = fmaf(P, h.z, Sv[j].z);
        h.w = fmaf(P, h.w, Sv[j].w);
    }
    g_Ssup[(b * NSUP + s) * D4 + d4] = h;
}

// ---------------------------------------------------------------------------
// Pass 2b: scan over the 8 superchunks. Grid (D4/256, BB) = 8 blocks (tiny).
// ---------------------------------------------------------------------------
__global__ void pass2b_kernel()
{
    const int d4 = blockIdx.x * 256 + threadIdx.x;
    const int b  = blockIdx.y;

    __shared__ float sPs[NSUP];
    if (threadIdx.x < NSUP) sPs[threadIdx.x] = g_Psup[b * NSUP + threadIdx.x];
    __syncthreads();

    const int base = b * NSUP * D4 + d4;
    float4 Sv[NSUP];
#pragma unroll
    for (int s = 0; s < NSUP; s++)
        Sv[s] = g_Ssup[base + s * D4];

    float4 h = make_float4(0.f, 0.f, 0.f, 0.f);
#pragma unroll
    for (int s = 0; s < NSUP; s++) {
        g_Hsup[base + s * D4] = h;
        const float P = sPs[s];
        h.x = fmaf(P, h.x, Sv[s].x);
        h.y = fmaf(P, h.y, Sv[s].y);
        h.z = fmaf(P, h.z, Sv[s].z);
        h.w = fmaf(P, h.w, Sv[s].w);
    }
}

// ---------------------------------------------------------------------------
// Pass 3: recompute in-chunk states with full carry-in, expand to out.
// h_in = Hin_local + W_c * Hsup.  All loads front-batched; streaming stores.
// ---------------------------------------------------------------------------
__global__ void pass3_kernel(const float4* __restrict__ hid4,
                             float4* __restrict__ out4)
{
    const int d4  = blockIdx.x * 256 + threadIdx.x;
    const int c   = blockIdx.y;
    const int b   = blockIdx.z;
    const int tid = threadIdx.x;

    __shared__ float4 sp[TT];
    __shared__ int    spos[TT + 1];
    __shared__ int    s_cnt_sh;
    __shared__ float  s_W;

    if (tid < TT) sp[tid] = g_PADT[b * MM + c * TT + tid];
    if (tid <= TT) {
        const int idx = c * TT + tid;
        spos[tid] = (idx < MM) ? g_POS[b * MM + idx] : LL;
    }
    if (tid == 255) { s_cnt_sh = min(g_count[b], MM); s_W = g_W[b * CC + c]; }
    __syncthreads();
    const int cnt = s_cnt_sh;
    const float W = s_W;

    // Issue carry loads FIRST so they overlap the hv batch (same MLP window).
    const float4 hloc = g_Hin4[(b * CC + c) * D4 + d4];
    const float4 hsup = g_Hsup[(b * NSUP + c / SUPLEN) * D4 + d4];

    const float4* hptr = hid4 + (size_t)(b * MM + c * TT) * D4 + d4;
    float4 hv[TT];
#pragma unroll
    for (int t = 0; t < TT; t++)
        hv[t] = __ldcg(hptr + (size_t)t * D4);

    float4 h;
    h.x = fmaf(W, hsup.x, hloc.x);
    h.y = fmaf(W, hsup.y, hloc.y);
    h.z = fmaf(W, hsup.z, hloc.z);
    h.w = fmaf(W, hsup.w, hloc.w);

    float4* outb = out4 + (size_t)b * LL * D4 + d4;

#pragma unroll
    for (int t = 0; t < TT; t++) {
        const float4 q = sp[t];
        h.x = fmaf(q.y, h.x, q.x * ((hv[t].x * q.w) * q.z));
        h.y = fmaf(q.y, h.y, q.x * ((hv[t].y * q.w) * q.z));
        h.z = fmaf(q.y, h.z, q.x * ((hv[t].z * q.w) * q.z));
        h.w = fmaf(q.y, h.w, q.x * ((hv[t].w * q.w) * q.z));

        const int tg = c * TT + t;
        if (tg < cnt) {
            const int start = spos[t];
            const int end   = (tg + 1 < cnt) ? spos[t + 1] : LL;
            for (int l = start; l < end; l++) {
                __stcs(outb + (size_t)l * D4, h);   // streaming 16B store
            }
        }
    }
}

// ---------------------------------------------------------------------------
// Inputs (metadata order = setup_inputs dict order):
//   d_in[0] hidden_states  float32 (B,M,D)
//   d_in[1] boundary_prob  float32 (B,L)
//   d_in[2] boundary_mask  bool    (B,L)  (dtype probed device-side)
//   d_in[3] mask                    -- unused by the reference
// Output: float32 (B,L,D)
// ---------------------------------------------------------------------------
extern "C" void kernel_launch(void* const* d_in, const int* in_sizes, int n_in,
                              void* d_out, int out_size)
{
    const float4* hid4 = (const float4*)d_in[0];
    const float*  bp   = (const float*)d_in[1];
    const void*   bm   = d_in[2];
    float4* out4 = (float4*)d_out;

    setup_kernel<<<BB, 512>>>(bp, bm);
    pass1_kernel<<<dim3(D4 / 256, CC, BB), 256>>>(hid4);
    pass2a_kernel<<<dim3(D4 / 256, NSUP, BB), 256>>>();
    pass2b_kernel<<<dim3(D4 / 256, BB), 256>>>();
    pass3_kernel<<<dim3(D4 / 256, CC, BB), 256>>>(hid4, out4);
}

// round 7
// speedup vs baseline: 1.4703x; 1.0661x over previous
#include <cuda_runtime.h>
#include <cuda_bf16.h>

// Problem shape (fixed by the dataset's setup_inputs)
#define BB 4
#define LL 4096
#define MM 2048
#define DD 2048
#define D4 (DD / 4)        // 512 float4 lanes
#define CC 128             // chunks along M
#define TT 16              // chunk length = MM / CC
#define NSUP 8             // superchunks
#define SUPLEN 16          // chunks per superchunk
#define EPSF 1e-4f

// Scratch (device globals: no allocation allowed in kernel_launch)
__device__ float4 g_PADT[BB * MM];          // per (b,t): {p, a=1-p, dt, 1/dt}
__device__ int    g_POS [BB * MM];          // position l of the t-th boundary
__device__ int    g_count[BB];              // boundaries per batch
__device__ float  g_P   [BB * CC];          // per-chunk product of a
__device__ float  g_W   [BB * CC];          // prefix product within superchunk
__device__ float  g_V   [BB * NSUP * NSUP]; // superchunk combine weights
__device__ float4 g_S4  [BB * CC * D4];     // per-chunk partial (zero carry-in)
__device__ float4 g_Hin4[BB * CC * D4];     // carry-in LOCAL to superchunk
__device__ float4 g_Ssup[BB * NSUP * D4];   // superchunk partial (zero carry-in)

// ---------------------------------------------------------------------------
// Setup: boundary scan, p gather (stable-sort semantics), scalar products.
// One block per batch, 512 threads, 8 tokens each.
// ---------------------------------------------------------------------------
__global__ void setup_kernel(const float* __restrict__ bp,
                             const void*  __restrict__ mask_raw)
{
    const int b   = blockIdx.x;
    const int tid = threadIdx.x;

    __shared__ int   s_is32;
    __shared__ int   s_cnt[512];
    __shared__ float s_a[MM];       // a = 1-p by sorted slot
    __shared__ float s_prod[CC];    // per-chunk products
    __shared__ float s_psup[NSUP];  // per-superchunk products

    // Probe mask dtype: int32 bools -> first 64 words all in {0,1};
    // packed uint8 bools (mixed pattern) -> some word > 1.
    if (tid == 0) {
        const int* w = (const int*)mask_raw;
        int ok = 1;
        for (int i = 0; i < 64; i++) {
            unsigned v = (unsigned)w[i];
            if (v > 1u) { ok = 0; break; }
        }
        s_is32 = ok;
    }
    __syncthreads();
    const bool is32 = (s_is32 != 0);

    int flags[8];
    const int base_l = tid * 8;
    int cnt = 0;
#pragma unroll
    for (int i = 0; i < 8; i++) {
        const int l = base_l + i;
        int f;
        if (is32) f = (((const int*)mask_raw)[b * LL + l] != 0);
        else      f = (((const unsigned char*)mask_raw)[b * LL + l] != 0);
        flags[i] = f;
        cnt += f;
    }
    s_cnt[tid] = cnt;
    __syncthreads();

    // Hillis-Steele inclusive scan over 512 per-thread counts
    for (int off = 1; off < 512; off <<= 1) {
        int v   = s_cnt[tid];
        int add = (tid >= off) ? s_cnt[tid - off] : 0;
        __syncthreads();
        s_cnt[tid] = v + add;
        __syncthreads();
    }
    const int total = s_cnt[511];
    int run = s_cnt[tid] - cnt;    // boundaries strictly before my first token
    if (tid == 0) g_count[b] = total;

    // Stable-sort position: boundaries first (in order), then non-boundaries.
#pragma unroll
    for (int i = 0; i < 8; i++) {
        const int l = base_l + i;
        int s;
        if (flags[i]) { s = run; run++; }
        else          { s = total + (l - run); }
        if (s < MM) {
            float p = bp[b * LL + l];
            p = fminf(fmaxf(p, EPSF), 1.0f - EPSF);
            const float a     = 1.0f - p;
            const float dt    = logf(1.0f / a);
            const float invdt = 1.0f / dt;
            g_PADT[b * MM + s] = make_float4(p, a, dt, invdt);
            s_a[s] = a;
            if (flags[i]) g_POS[b * MM + s] = l;
        }
    }
    __syncthreads();

    // Per-chunk products of a from smem (a <= 1-eps; underflow benign)
    if (tid < CC) {
        float prod = 1.0f;
#pragma unroll
        for (int i = 0; i < TT; i++) prod *= s_a[tid * TT + i];
        s_prod[tid] = prod;
        g_P[b * CC + tid] = prod;
    }
    __syncthreads();

    // Prefix product within superchunk: W_c = prod over chunks [sup_start, c)
    if (tid < CC) {
        const int s0 = (tid / SUPLEN) * SUPLEN;
        float w = 1.0f;
        for (int k = s0; k < tid; k++) w *= s_prod[k];
        g_W[b * CC + tid] = w;
    }
    // Superchunk product
    if (tid < NSUP) {
        float ps = 1.0f;
#pragma unroll
        for (int k = 0; k < SUPLEN; k++) ps *= s_prod[tid * SUPLEN + k];
        s_psup[tid] = ps;
    }
    __syncthreads();

    // Superchunk combine weights: V[s][s'] = prod Psup over (s', s); 0 if s'>=s.
    // Hsup[s] = sum_{s'<s} V[s][s'] * Ssup[s']  (expanded superchunk scan)
    if (tid < NSUP * NSUP) {
        const int s  = tid / NSUP;
        const int sp = tid % NSUP;
        float v = 0.0f;
        if (sp < s) {
            v = 1.0f;
            for (int k = sp + 1; k < s; k++) v *= s_psup[k];
        }
        g_V[(b * NSUP + s) * NSUP + sp] = v;
    }
}

// ---------------------------------------------------------------------------
// Pass 1: per-chunk partial EMA with zero carry-in -> g_S4.
// Grid (D4/256, CC, BB). Tile loads front-batched for MLP.
// ---------------------------------------------------------------------------
__global__ void pass1_kernel(const float4* __restrict__ hid4)
{
    const int d4 = blockIdx.x * 256 + threadIdx.x;
    const int c  = blockIdx.y;
    const int b  = blockIdx.z;

    __shared__ float4 sp[TT];
    if (threadIdx.x < TT)
        sp[threadIdx.x] = g_PADT[b * MM + c * TT + threadIdx.x];
    __syncthreads();

    const float4* hptr = hid4 + (size_t)(b * MM + c * TT) * D4 + d4;
    float4 hv[TT];
#pragma unroll
    for (int t = 0; t < TT; t++)
        hv[t] = __ldcg(hptr + (size_t)t * D4);   // L2-resident for pass3

    float4 S = make_float4(0.f, 0.f, 0.f, 0.f);
#pragma unroll
    for (int t = 0; t < TT; t++) {
        const float4 q = sp[t];
        S.x = fmaf(q.y, S.x, q.x * ((hv[t].x * q.w) * q.z));
        S.y = fmaf(q.y, S.y, q.x * ((hv[t].y * q.w) * q.z));
        S.z = fmaf(q.y, S.z, q.x * ((hv[t].z * q.w) * q.z));
        S.w = fmaf(q.y, S.w, q.x * ((hv[t].w * q.w) * q.z));
    }
    __stcg(&g_S4[(b * CC + c) * D4 + d4], S);    // keep in L2 for pass2a
}

// ---------------------------------------------------------------------------
// Pass 2a: within-superchunk scan. Grid (D4/256, NSUP, BB) = 64 blocks.
// Produces carry-in LOCAL to the superchunk + superchunk aggregate.
// ---------------------------------------------------------------------------
__global__ void pass2a_kernel()
{
    const int d4 = blockIdx.x * 256 + threadIdx.x;
    const int s  = blockIdx.y;
    const int b  = blockIdx.z;

    __shared__ float sP[SUPLEN];
    if (threadIdx.x < SUPLEN)
        sP[threadIdx.x] = g_P[b * CC + s * SUPLEN + threadIdx.x];
    __syncthreads();

    const int base = (b * CC + s * SUPLEN) * D4 + d4;
    float4 Sv[SUPLEN];
#pragma unroll
    for (int j = 0; j < SUPLEN; j++)
        Sv[j] = __ldcg(&g_S4[base + j * D4]);

    float4 h = make_float4(0.f, 0.f, 0.f, 0.f);
#pragma unroll
    for (int j = 0; j < SUPLEN; j++) {
        __stcg(&g_Hin4[base + j * D4], h);       // L2-resident for pass3
        const float P = sP[j];
        h.x = fmaf(P, h.x, Sv[j].x);
        h.y = fmaf(P, h.y, Sv[j].y);
        h.z = fmaf(P, h.z, Sv[j].z);
        h.w = fmaf(P, h.w, Sv[j].w);
    }
    __stcg(&g_Ssup[(b * NSUP + s) * D4 + d4], h);
}

// ---------------------------------------------------------------------------
// Pass 3: recompute in-chunk states with full carry-in, expand to out.
// h_in = Hin_local + W_c * sum_{s'<sup} V[sup][s'] * Ssup[s']
// (superchunk scan folded in via scalar weights -- no pass2b kernel).
// All loads front-batched; streaming stores.
// ---------------------------------------------------------------------------
__global__ void pass3_kernel(const float4* __restrict__ hid4,
                             float4* __restrict__ out4)
{
    const int d4  = blockIdx.x * 256 + threadIdx.x;
    const int c   = blockIdx.y;
    const int b   = blockIdx.z;
    const int tid = threadIdx.x;
    const int sup = c / SUPLEN;      // uniform per block

    __shared__ float4 sp[TT];
    __shared__ int    spos[TT + 1];
    __shared__ int    s_cnt_sh;
    __shared__ float  s_W;
    __shared__ float  s_V[NSUP];

    if (tid < TT) sp[tid] = g_PADT[b * MM + c * TT + tid];
    if (tid <= TT) {
        const int idx = c * TT + tid;
        spos[tid] = (idx < MM) ? g_POS[b * MM + idx] : LL;
    }
    if (tid < NSUP) s_V[tid] = g_V[(b * NSUP + sup) * NSUP + tid];
    if (tid == 255) { s_cnt_sh = min(g_count[b], MM); s_W = g_W[b * CC + c]; }
    __syncthreads();
    const int cnt = s_cnt_sh;
    const float W = s_W;

    // Front-batch ALL independent loads: local carry, Ssup prefixes, hv tile.
    const float4 hloc = __ldcg(&g_Hin4[(b * CC + c) * D4 + d4]);

    float4 ssv[NSUP - 1];
#pragma unroll
    for (int j = 0; j < NSUP - 1; j++) {
        if (j < sup) ssv[j] = __ldcg(&g_Ssup[(b * NSUP + j) * D4 + d4]);
        else         ssv[j] = make_float4(0.f, 0.f, 0.f, 0.f);
    }

    const float4* hptr = hid4 + (size_t)(b * MM + c * TT) * D4 + d4;
    float4 hv[TT];
#pragma unroll
    for (int t = 0; t < TT; t++)
        hv[t] = __ldcg(hptr + (size_t)t * D4);

    // Combine superchunk prefix contributions with scalar weights.
    float4 acc = make_float4(0.f, 0.f, 0.f, 0.f);
#pragma unroll
    for (int j = 0; j < NSUP - 1; j++) {
        const float v = s_V[j];      // 0 for j >= sup
        acc.x = fmaf(v, ssv[j].x, acc.x);
        acc.y = fmaf(v, ssv[j].y, acc.y);
        acc.z = fmaf(v, ssv[j].z, acc.z);
        acc.w = fmaf(v, ssv[j].w, acc.w);
    }

    float4 h;
    h.x = fmaf(W, acc.x, hloc.x);
    h.y = fmaf(W, acc.y, hloc.y);
    h.z = fmaf(W, acc.z, hloc.z);
    h.w = fmaf(W, acc.w, hloc.w);

    float4* outb = out4 + (size_t)b * LL * D4 + d4;

#pragma unroll
    for (int t = 0; t < TT; t++) {
        const float4 q = sp[t];
        h.x = fmaf(q.y, h.x, q.x * ((hv[t].x * q.w) * q.z));
        h.y = fmaf(q.y, h.y, q.x * ((hv[t].y * q.w) * q.z));
        h.z = fmaf(q.y, h.z, q.x * ((hv[t].z * q.w) * q.z));
        h.w = fmaf(q.y, h.w, q.x * ((hv[t].w * q.w) * q.z));

        const int tg = c * TT + t;
        if (tg < cnt) {
            const int start = spos[t];
            const int end   = (tg + 1 < cnt) ? spos[t + 1] : LL;
            for (int l = start; l < end; l++) {
                __stcs(outb + (size_t)l * D4, h);   // streaming 16B store
            }
        }
    }
}

// ---------------------------------------------------------------------------
// Inputs (metadata order = setup_inputs dict order):
//   d_in[0] hidden_states  float32 (B,M,D)
//   d_in[1] boundary_prob  float32 (B,L)
//   d_in[2] boundary_mask  bool    (B,L)  (dtype probed device-side)
//   d_in[3] mask                    -- unused by the reference
// Output: float32 (B,L,D)
// ---------------------------------------------------------------------------
extern "C" void kernel_launch(void* const* d_in, const int* in_sizes, int n_in,
                              void* d_out, int out_size)
{
    const float4* hid4 = (const float4*)d_in[0];
    const float*  bp   = (const float*)d_in[1];
    const void*   bm   = d_in[2];
    float4* out4 = (float4*)d_out;

    setup_kernel<<<BB, 512>>>(bp, bm);
    pass1_kernel<<<dim3(D4 / 256, CC, BB), 256>>>(hid4);
    pass2a_kernel<<<dim3(D4 / 256, NSUP, BB), 256>>>();
    pass3_kernel<<<dim3(D4 / 256, CC, BB), 256>>>(hid4, out4);
}